// round 2
// baseline (speedup 1.0000x reference)
#include <cuda_runtime.h>

#define BB 512
#define TT 512
#define DD 128
#define LL 256
#define G4 1024
#define NCTA 128
#define NTHR 256

// Persistent state (allowed: __device__ globals, no allocation)
__device__ float g_H[2][BB][LL];          // double-buffered hidden state
__device__ unsigned int g_count;          // barrier arrive counter (returns to 0)
__device__ unsigned int g_gen;            // barrier generation (monotonic)

__device__ __forceinline__ void grid_barrier() {
    __syncthreads();
    if (threadIdx.x == 0) {
        volatile unsigned int* genp = &g_gen;
        unsigned int g = *genp;
        __threadfence();
        if (atomicAdd(&g_count, 1u) == NCTA - 1u) {
            g_count = 0u;
            __threadfence();
            *genp = g + 1u;
        } else {
            while (*genp == g) { }
        }
        __threadfence();
    }
    __syncthreads();
}

__device__ __forceinline__ float sigm(float x) { return 1.0f / (1.0f + __expf(-x)); }

// acc[4][4] += A[rows][k] * Wsm[cols][k]   (W stored transposed [col][k] in smem)
__device__ __forceinline__ void gemm_part(
    const float* __restrict__ A, int aStride, int rowBase,
    const float* __restrict__ wsm, int wStride, int wOff, int kcnt,
    float acc[4][4], int tx, int ty)
{
    const float* arow = A + (rowBase + tx * 4) * aStride;
    const float* wrow = wsm + (ty * 4) * wStride + wOff;
    #pragma unroll 4
    for (int k = 0; k < kcnt; k += 4) {
        float4 av[4], wv[4];
        #pragma unroll
        for (int i = 0; i < 4; i++)
            av[i] = *reinterpret_cast<const float4*>(arow + i * aStride + k);
        #pragma unroll
        for (int j = 0; j < 4; j++)
            wv[j] = *reinterpret_cast<const float4*>(wrow + j * wStride + k);
        #pragma unroll
        for (int i = 0; i < 4; i++) {
            #pragma unroll
            for (int j = 0; j < 4; j++) {
                acc[i][j] = fmaf(av[i].x, wv[j].x, acc[i][j]);
                acc[i][j] = fmaf(av[i].y, wv[j].y, acc[i][j]);
                acc[i][j] = fmaf(av[i].z, wv[j].z, acc[i][j]);
                acc[i][j] = fmaf(av[i].w, wv[j].w, acc[i][j]);
            }
        }
    }
}

// One LSTM layer step for this CTA's tile: rows [b0, b0+128), 8 hidden units (nb).
// z-cols owned: {g*256 + nb*8 + u : g in 0..3, u in 0..7} -> local col = g*8+u.
__device__ __forceinline__ void lstm_tile_step(
    const float* __restrict__ Ax, int axStride, int kx,
    const float* __restrict__ Ah,
    const float* __restrict__ wsm, int wStride,
    const float* __restrict__ bsm,
    float* __restrict__ zsm,
    float c[4],
    float* __restrict__ hOut,
    int b0, int nb, int tx, int ty)
{
    float acc[4][4];
    #pragma unroll
    for (int i = 0; i < 4; i++)
        #pragma unroll
        for (int j = 0; j < 4; j++)
            acc[i][j] = bsm[ty * 4 + j];

    if (kx > 0)
        gemm_part(Ax, axStride, b0, wsm, wStride, 0, kx, acc, tx, ty);
    gemm_part(Ah, LL, b0, wsm, wStride, kx, LL, acc, tx, ty);

    // exchange z across threads (each thread holds one gate's cols; needs all 4 gates)
    #pragma unroll
    for (int i = 0; i < 4; i++)
        #pragma unroll
        for (int j = 0; j < 4; j++)
            zsm[(tx * 4 + i) * 32 + ty * 4 + j] = acc[i][j];
    __syncthreads();

    #pragma unroll
    for (int i = 0; i < 4; i++) {
        int row = tx * 4 + i;
        float zi = zsm[row * 32 + ty];
        float zf = zsm[row * 32 + 8 + ty];
        float zg = zsm[row * 32 + 16 + ty];
        float zo = zsm[row * 32 + 24 + ty];
        float ig = sigm(zi);
        float fg = sigm(zf);
        float gg = fmaxf(zg, 0.0f);
        float og = sigm(zo);
        float cn = fg * c[i] + ig * gg;
        c[i] = cn;
        hOut[(b0 + row) * LL + nb * 8 + ty] = og * fmaxf(cn, 0.0f);
    }
}

extern "C" __global__ void __launch_bounds__(NTHR, 1)
lstm_ae_kernel(const float* __restrict__ encIn, const float* __restrict__ decIn,
               const float* __restrict__ W0, const float* __restrict__ U0, const float* __restrict__ b0g,
               const float* __restrict__ W1, const float* __restrict__ U1, const float* __restrict__ b1g,
               const float* __restrict__ Wd, const float* __restrict__ Ud, const float* __restrict__ bdg,
               const float* __restrict__ Wo, const float* __restrict__ bog,
               float* __restrict__ outp)
{
    extern __shared__ float smem[];
    float* w0sm = smem;                 // [32][384]  W0|U0 slice, transposed
    float* w1sm = w0sm + 32 * 384;      // [32][256]  (W1+U1) slice
    float* wdsm = w1sm + 32 * 256;      // [32][384]  Wd|Ud slice
    float* wosm = wdsm + 32 * 384;      // [4][256]   out_W slice
    float* b0sm = wosm + 4 * 256;       // 32
    float* b1sm = b0sm + 32;            // 32
    float* bdsm = b1sm + 32;            // 32
    float* bosm = bdsm + 32;            // 4 (+pad 12)
    float* zsm  = bosm + 16;            // [128][32]

    int tid = threadIdx.x;
    int nb = blockIdx.x & 31;           // hidden-unit block (8 units)
    int rb = blockIdx.x >> 5;           // row block (128 rows)
    int b0 = rb * 128;
    int tx = tid & 31;                  // row group: rows tx*4..tx*4+3
    int ty = tid >> 5;                  // col group: cols ty*4..ty*4+3 (gate ty/2)

    // ---- one-time weight preload into smem (transposed [col][k]) ----
    for (int idx = tid; idx < 32 * 384; idx += NTHR) {
        int j = idx / 384, k = idx % 384;
        int gcol = (j >> 3) * LL + nb * 8 + (j & 7);
        w0sm[idx] = (k < DD) ? W0[k * G4 + gcol] : U0[(k - DD) * G4 + gcol];
        wdsm[idx] = (k < DD) ? Wd[k * G4 + gcol] : Ud[(k - DD) * G4 + gcol];
    }
    for (int idx = tid; idx < 32 * 256; idx += NTHR) {
        int j = idx / 256, k = idx % 256;
        int gcol = (j >> 3) * LL + nb * 8 + (j & 7);
        w1sm[idx] = W1[k * G4 + gcol] + U1[k * G4 + gcol];   // fused: x == h for layer 1
    }
    for (int idx = tid; idx < 4 * 256; idx += NTHR) {
        int j = idx / 256, k = idx % 256;
        wosm[idx] = Wo[k * DD + nb * 4 + j];
    }
    if (tid < 32) {
        int gcol = (tid >> 3) * LL + nb * 8 + (tid & 7);
        b0sm[tid] = b0g[gcol];
        b1sm[tid] = b1g[gcol];
        bdsm[tid] = bdg[gcol];
    }
    if (tid < 4) bosm[tid] = bog[nb * 4 + tid];

    // zero both H buffers
    float* hflat = &g_H[0][0][0];
    for (int idx = blockIdx.x * NTHR + tid; idx < 2 * BB * LL; idx += NCTA * NTHR)
        hflat[idx] = 0.0f;

    float c[4] = {0.0f, 0.0f, 0.0f, 0.0f};   // shared (h,c) chain through ALL layers
    grid_barrier();

    int cur = 0;
    // ---------------- encoder: 512 steps x 2 layers ----------------
    for (int t = 0; t < TT; t++) {
        // layer 0: z = x_t @ W0 + h @ U0 + b0
        lstm_tile_step(encIn + t * DD, TT * DD, DD, &g_H[cur][0][0],
                       w0sm, 384, b0sm, zsm, c, &g_H[cur ^ 1][0][0], b0, nb, tx, ty);
        grid_barrier();
        cur ^= 1;
        // layer 1 (fused W1+U1, K=256): z = h' @ (W1+U1) + b1
        lstm_tile_step(nullptr, 0, 0, &g_H[cur][0][0],
                       w1sm, 256, b1sm, zsm, c, &g_H[cur ^ 1][0][0], b0, nb, tx, ty);
        grid_barrier();
        cur ^= 1;
    }
    // ---------------- decoder: 512 autoregressive steps ----------------
    for (int t = 0; t < TT; t++) {
        const float* xsrc = (t == 0) ? decIn : (outp + (t - 1) * DD);
        lstm_tile_step(xsrc, TT * DD, DD, &g_H[cur][0][0],
                       wdsm, 384, bdsm, zsm, c, &g_H[cur ^ 1][0][0], b0, nb, tx, ty);
        grid_barrier();
        cur ^= 1;
        // out = h @ out_W + out_b  -> d_out[b][t][:] (also next step's input)
        {
            int row = tid & 127;
            int jb = (tid >> 7) * 2;
            const float* hrow = &g_H[cur][b0 + row][0];
            const float* wa = wosm + jb * LL;
            const float* wb = wosm + (jb + 1) * LL;
            float s0 = bosm[jb], s1 = bosm[jb + 1];
            #pragma unroll 8
            for (int k = 0; k < LL; k += 4) {
                float4 h4 = *reinterpret_cast<const float4*>(hrow + k);
                float4 a4 = *reinterpret_cast<const float4*>(wa + k);
                float4 b4 = *reinterpret_cast<const float4*>(wb + k);
                s0 = fmaf(h4.x, a4.x, s0); s0 = fmaf(h4.y, a4.y, s0);
                s0 = fmaf(h4.z, a4.z, s0); s0 = fmaf(h4.w, a4.w, s0);
                s1 = fmaf(h4.x, b4.x, s1); s1 = fmaf(h4.y, b4.y, s1);
                s1 = fmaf(h4.z, b4.z, s1); s1 = fmaf(h4.w, b4.w, s1);
            }
            float* orow = outp + (b0 + row) * (TT * DD) + t * DD + nb * 4;
            orow[jb]     = s0;
            orow[jb + 1] = s1;
        }
        grid_barrier();
    }
}

extern "C" void kernel_launch(void* const* d_in, const int* in_sizes, int n_in,
                              void* d_out, int out_size)
{
    const float* encIn = (const float*)d_in[0];
    const float* decIn = (const float*)d_in[1];
    const float* W0    = (const float*)d_in[2];
    const float* U0    = (const float*)d_in[3];
    const float* b0    = (const float*)d_in[4];
    const float* W1    = (const float*)d_in[5];
    const float* U1    = (const float*)d_in[6];
    const float* b1    = (const float*)d_in[7];
    const float* Wd    = (const float*)d_in[8];
    const float* Ud    = (const float*)d_in[9];
    const float* bd    = (const float*)d_in[10];
    const float* Wo    = (const float*)d_in[11];
    const float* bo    = (const float*)d_in[12];
    float* outp = (float*)d_out;

    // smem: 32*384 + 32*256 + 32*384 + 4*256 + 32*3 + 16 + 128*32 = 38000 floats
    size_t smem_bytes = 38000 * sizeof(float);
    cudaFuncSetAttribute((const void*)lstm_ae_kernel,
                         cudaFuncAttributeMaxDynamicSharedMemorySize, (int)smem_bytes);

    lstm_ae_kernel<<<NCTA, NTHR, smem_bytes>>>(
        encIn, decIn, W0, U0, b0, W1, U1, b1, Wd, Ud, bd, Wo, bo, outp);
}

// round 3
// speedup vs baseline: 2.1403x; 2.1403x over previous
#include <cuda_runtime.h>

#define BB 512
#define TT 512
#define DD 128
#define LL 256
#define G4 1024
#define NCTA 128
#define NTHR 256

// Persistent state (static __device__ globals — no allocation)
__device__ float g_H[2][LL][BB];          // hidden state, TRANSPOSED [feature][batch]
__device__ float g_encT[TT][DD][BB];      // encoder inputs transposed (128MB)
__device__ float g_xdT[2][DD][BB];        // decoder input ping-pong, transposed
__device__ unsigned int g_count;
__device__ unsigned int g_gen;

__device__ __forceinline__ void grid_barrier() {
    __syncthreads();
    if (threadIdx.x == 0) {
        volatile unsigned int* genp = &g_gen;
        unsigned int g = *genp;
        __threadfence();
        if (atomicAdd(&g_count, 1u) == NCTA - 1u) {
            g_count = 0u;
            __threadfence();
            *genp = g + 1u;
        } else {
            while (*genp == g) { }
        }
        __threadfence();
    }
    __syncthreads();
}

__device__ __forceinline__ float sigm(float x) { return 1.0f / (1.0f + __expf(-x)); }

// acc[i][j] += A[k][colBase+i] * W[k][ty*4+j]
// A is [K][BB] (batch contiguous -> coalesced LDG.128 across lanes)
// wsm is [K][32] (warp-uniform broadcast LDS.128)
__device__ __forceinline__ void gemm_T(
    const float* __restrict__ A, int colBase,
    const float* __restrict__ wsm, int kcnt,
    float acc[4][4], int ty)
{
    const float* aP = A + colBase;
    const float* wP = wsm + ty * 4;
    #pragma unroll 8
    for (int k = 0; k < kcnt; k++) {
        float4 av = *reinterpret_cast<const float4*>(aP + k * BB);
        float4 wv = *reinterpret_cast<const float4*>(wP + k * 32);
        acc[0][0] = fmaf(av.x, wv.x, acc[0][0]);
        acc[0][1] = fmaf(av.x, wv.y, acc[0][1]);
        acc[0][2] = fmaf(av.x, wv.z, acc[0][2]);
        acc[0][3] = fmaf(av.x, wv.w, acc[0][3]);
        acc[1][0] = fmaf(av.y, wv.x, acc[1][0]);
        acc[1][1] = fmaf(av.y, wv.y, acc[1][1]);
        acc[1][2] = fmaf(av.y, wv.z, acc[1][2]);
        acc[1][3] = fmaf(av.y, wv.w, acc[1][3]);
        acc[2][0] = fmaf(av.z, wv.x, acc[2][0]);
        acc[2][1] = fmaf(av.z, wv.y, acc[2][1]);
        acc[2][2] = fmaf(av.z, wv.z, acc[2][2]);
        acc[2][3] = fmaf(av.z, wv.w, acc[2][3]);
        acc[3][0] = fmaf(av.w, wv.x, acc[3][0]);
        acc[3][1] = fmaf(av.w, wv.y, acc[3][1]);
        acc[3][2] = fmaf(av.w, wv.z, acc[3][2]);
        acc[3][3] = fmaf(av.w, wv.w, acc[3][3]);
    }
}

// One LSTM layer step for this CTA: rows [b0,b0+128), 8 hidden units (block nb).
// local z-col lc in 0..31 maps gcol = (lc>>3)*L + nb*8 + (lc&7) (gate-major).
__device__ __forceinline__ void lstm_step_T(
    const float* __restrict__ Ax, int kx,          // [kx][BB] or null
    const float* __restrict__ Ah,                  // [LL][BB]
    const float* __restrict__ wsm,                 // [(kx+LL)][32]
    const float* __restrict__ bsm,
    float* __restrict__ zsm,
    float c[4],
    float* __restrict__ hOutT,                     // [LL][BB]
    int b0, int nb, int tx, int ty)
{
    float acc[4][4];
    #pragma unroll
    for (int i = 0; i < 4; i++)
        #pragma unroll
        for (int j = 0; j < 4; j++)
            acc[i][j] = bsm[ty * 4 + j];

    int colBase = b0 + tx * 4;
    if (kx > 0)
        gemm_T(Ax, colBase, wsm, kx, acc, ty);
    gemm_T(Ah, colBase, wsm + kx * 32, LL, acc, ty);

    // exchange z (thread holds cols of one gate-group; activation needs all 4 gates)
    #pragma unroll
    for (int i = 0; i < 4; i++)
        #pragma unroll
        for (int j = 0; j < 4; j++)
            zsm[(tx * 4 + i) * 32 + ty * 4 + j] = acc[i][j];
    __syncthreads();

    #pragma unroll
    for (int i = 0; i < 4; i++) {
        int row = tx * 4 + i;
        float zi = zsm[row * 32 + ty];
        float zf = zsm[row * 32 + 8 + ty];
        float zg = zsm[row * 32 + 16 + ty];
        float zo = zsm[row * 32 + 24 + ty];
        float ig = sigm(zi);
        float fg = sigm(zf);
        float gg = fmaxf(zg, 0.0f);
        float og = sigm(zo);
        float cn = fg * c[i] + ig * gg;
        c[i] = cn;
        hOutT[(nb * 8 + ty) * BB + b0 + row] = og * fmaxf(cn, 0.0f);
    }
    __syncthreads();   // protect zsm reuse
}

// Tiled transpose: encIn[b][t][k] -> g_encT[t][k][b]
extern "C" __global__ void __launch_bounds__(256)
transpose_enc_kernel(const float* __restrict__ in)
{
    __shared__ float tile[32][33];
    int t  = blockIdx.z;
    int k0 = blockIdx.y * 32;
    int b0 = blockIdx.x * 32;
    int tx = threadIdx.x, ty = threadIdx.y;  // 32 x 8
    #pragma unroll
    for (int i = 0; i < 32; i += 8)
        tile[ty + i][tx] = in[(size_t)(b0 + ty + i) * (TT * DD) + t * DD + k0 + tx];
    __syncthreads();
    #pragma unroll
    for (int i = 0; i < 32; i += 8)
        g_encT[t][k0 + ty + i][b0 + tx] = tile[tx][ty + i];
}

extern "C" __global__ void __launch_bounds__(NTHR, 1)
lstm_ae_kernel(const float* __restrict__ decIn,
               const float* __restrict__ W0, const float* __restrict__ U0, const float* __restrict__ b0g,
               const float* __restrict__ W1, const float* __restrict__ U1, const float* __restrict__ b1g,
               const float* __restrict__ Wd, const float* __restrict__ Ud, const float* __restrict__ bdg,
               const float* __restrict__ Wo, const float* __restrict__ bog,
               float* __restrict__ outp)
{
    extern __shared__ float smem[];
    float* w0sm = smem;                 // [384][32]
    float* w1sm = w0sm + 384 * 32;      // [256][32]  (W1+U1 fused: x == h for layer 1)
    float* wdsm = w1sm + 256 * 32;      // [384][32]
    float* wosm = wdsm + 384 * 32;      // [256][4]
    float* b0sm = wosm + 256 * 4;       // 32
    float* b1sm = b0sm + 32;            // 32
    float* bdsm = b1sm + 32;            // 32
    float* bosm = bdsm + 32;            // 4 (+12 pad)
    float* zsm  = bosm + 16;            // [128][32]

    int tid = threadIdx.x;
    int nb = blockIdx.x & 31;           // hidden-unit block (8 units)
    int rb = blockIdx.x >> 5;           // row block (128 batch rows)
    int b0 = rb * 128;
    int tx = tid & 31;                  // batch group: rows tx*4..+3
    int ty = tid >> 5;                  // col group (warp-uniform -> smem broadcast)

    // ---- one-time weight preload, layout [k][32 local cols] ----
    for (int idx = tid; idx < 384 * 32; idx += NTHR) {
        int k = idx >> 5, lc = idx & 31;
        int gcol = (lc >> 3) * LL + nb * 8 + (lc & 7);
        w0sm[idx] = (k < DD) ? W0[k * G4 + gcol] : U0[(k - DD) * G4 + gcol];
        wdsm[idx] = (k < DD) ? Wd[k * G4 + gcol] : Ud[(k - DD) * G4 + gcol];
    }
    for (int idx = tid; idx < 256 * 32; idx += NTHR) {
        int k = idx >> 5, lc = idx & 31;
        int gcol = (lc >> 3) * LL + nb * 8 + (lc & 7);
        w1sm[idx] = W1[k * G4 + gcol] + U1[k * G4 + gcol];
    }
    for (int idx = tid; idx < 256 * 4; idx += NTHR) {
        int k = idx >> 2, j = idx & 3;
        wosm[idx] = Wo[k * DD + nb * 4 + j];
    }
    if (tid < 32) {
        int gcol = (tid >> 3) * LL + nb * 8 + (tid & 7);
        b0sm[tid] = b0g[gcol];
        b1sm[tid] = b1g[gcol];
        bdsm[tid] = bdg[gcol];
    }
    if (tid < 4) bosm[tid] = bog[nb * 4 + tid];

    // zero both H buffers; init decoder x(t=0) transposed
    {
        int gtid = blockIdx.x * NTHR + tid;
        float* hflat = &g_H[0][0][0];
        for (int idx = gtid; idx < 2 * LL * BB; idx += NCTA * NTHR)
            hflat[idx] = 0.0f;
        for (int idx = gtid; idx < DD * BB; idx += NCTA * NTHR) {
            int k = idx >> 9, b = idx & 511;
            g_xdT[0][k][b] = decIn[(size_t)b * (TT * DD) + k];
        }
    }

    float c[4] = {0.0f, 0.0f, 0.0f, 0.0f};
    grid_barrier();

    int cur = 0;
    // ---------------- encoder ----------------
    for (int t = 0; t < TT; t++) {
        lstm_step_T(&g_encT[t][0][0], DD, &g_H[cur][0][0],
                    w0sm, b0sm, zsm, c, &g_H[cur ^ 1][0][0], b0, nb, tx, ty);
        grid_barrier();
        cur ^= 1;
        lstm_step_T(nullptr, 0, &g_H[cur][0][0],
                    w1sm, b1sm, zsm, c, &g_H[cur ^ 1][0][0], b0, nb, tx, ty);
        grid_barrier();
        cur ^= 1;
    }
    // ---------------- decoder ----------------
    for (int t = 0; t < TT; t++) {
        lstm_step_T(&g_xdT[t & 1][0][0], DD, &g_H[cur][0][0],
                    wdsm, bdsm, zsm, c, &g_H[cur ^ 1][0][0], b0, nb, tx, ty);
        grid_barrier();
        cur ^= 1;

        // out = h @ out_W + out_b : CTA computes its 4 out-cols for 128 rows.
        // thread: b = tid&127 (one row), half = tid>>7 (K split), combine in zsm.
        {
            int b = tid & 127;
            int half = tid >> 7;
            const float* hP = &g_H[cur][half * 128][b0 + b];
            const float* wP = wosm + half * 128 * 4;
            float s0, s1, s2, s3;
            if (half == 0) { s0 = bosm[0]; s1 = bosm[1]; s2 = bosm[2]; s3 = bosm[3]; }
            else           { s0 = s1 = s2 = s3 = 0.0f; }
            #pragma unroll 8
            for (int kk = 0; kk < 128; kk++) {
                float h = hP[kk * BB];
                float4 w4 = *reinterpret_cast<const float4*>(wP + kk * 4);
                s0 = fmaf(h, w4.x, s0);
                s1 = fmaf(h, w4.y, s1);
                s2 = fmaf(h, w4.z, s2);
                s3 = fmaf(h, w4.w, s3);
            }
            if (half) {
                zsm[b * 4 + 0] = s0; zsm[b * 4 + 1] = s1;
                zsm[b * 4 + 2] = s2; zsm[b * 4 + 3] = s3;
            }
            __syncthreads();
            if (!half) {
                s0 += zsm[b * 4 + 0]; s1 += zsm[b * 4 + 1];
                s2 += zsm[b * 4 + 2]; s3 += zsm[b * 4 + 3];
                float4 o = make_float4(s0, s1, s2, s3);
                *reinterpret_cast<float4*>(outp + (size_t)(b0 + b) * (TT * DD) + t * DD + nb * 4) = o;
                int nxt = (t + 1) & 1;
                g_xdT[nxt][nb * 4 + 0][b0 + b] = s0;
                g_xdT[nxt][nb * 4 + 1][b0 + b] = s1;
                g_xdT[nxt][nb * 4 + 2][b0 + b] = s2;
                g_xdT[nxt][nb * 4 + 3][b0 + b] = s3;
            }
        }
        grid_barrier();
    }
}

extern "C" void kernel_launch(void* const* d_in, const int* in_sizes, int n_in,
                              void* d_out, int out_size)
{
    const float* encIn = (const float*)d_in[0];
    const float* decIn = (const float*)d_in[1];
    const float* W0    = (const float*)d_in[2];
    const float* U0    = (const float*)d_in[3];
    const float* b0    = (const float*)d_in[4];
    const float* W1    = (const float*)d_in[5];
    const float* U1    = (const float*)d_in[6];
    const float* b1    = (const float*)d_in[7];
    const float* Wd    = (const float*)d_in[8];
    const float* Ud    = (const float*)d_in[9];
    const float* bd    = (const float*)d_in[10];
    const float* Wo    = (const float*)d_in[11];
    const float* bo    = (const float*)d_in[12];
    float* outp = (float*)d_out;

    // 1) transpose encoder inputs into g_encT
    {
        dim3 grid(BB / 32, DD / 32, TT);
        dim3 block(32, 8);
        transpose_enc_kernel<<<grid, block>>>(encIn);
    }

    // 2) persistent LSTM kernel
    size_t smem_bytes = 38000 * sizeof(float);
    cudaFuncSetAttribute((const void*)lstm_ae_kernel,
                         cudaFuncAttributeMaxDynamicSharedMemorySize, (int)smem_bytes);
    lstm_ae_kernel<<<NCTA, NTHR, smem_bytes>>>(
        decIn, W0, U0, b0, W1, U1, b1, Wd, Ud, bd, Wo, bo, outp);
}

// round 4
// speedup vs baseline: 4.1420x; 1.9352x over previous
#include <cuda_runtime.h>

#define BB 512
#define TT 512
#define DD 128
#define LL 256
#define G4 1024
#define NCTA 128
#define NTHR 512
#define ZST 33   // zsm row stride (bank-conflict pad)

typedef unsigned long long ull;

// Persistent state (static __device__ globals — no allocation)
__device__ float g_H[2][LL][BB];          // hidden state [feature][batch]
__device__ float g_encT[TT][DD][BB];      // encoder inputs transposed
__device__ float g_xdT[2][DD][BB];        // decoder input ping-pong, transposed
__device__ unsigned int g_count;
__device__ unsigned int g_gen;

__device__ __forceinline__ void grid_barrier() {
    __syncthreads();
    if (threadIdx.x == 0) {
        volatile unsigned int* genp = &g_gen;
        unsigned int g = *genp;
        __threadfence();
        if (atomicAdd(&g_count, 1u) == NCTA - 1u) {
            g_count = 0u;
            __threadfence();
            *genp = g + 1u;
        } else {
            while (*genp == g) { }
        }
        __threadfence();
    }
    __syncthreads();
}

__device__ __forceinline__ float sigm(float x) { return 1.0f / (1.0f + __expf(-x)); }

__device__ __forceinline__ ull pack2(float lo, float hi) {
    ull r; asm("mov.b64 %0, {%1, %2};" : "=l"(r) : "f"(lo), "f"(hi)); return r;
}
__device__ __forceinline__ void unpack2(ull v, float& lo, float& hi) {
    asm("mov.b64 {%0, %1}, %2;" : "=f"(lo), "=f"(hi) : "l"(v));
}
__device__ __forceinline__ void ffma2(ull& d, ull a, ull b) {
    asm("fma.rn.f32x2 %0, %1, %2, %0;" : "+l"(d) : "l"(a), "l"(b));
}

// acc[rp][j] (+)= A[k][col..col+3] * W[k][ty4+j]  using packed f32x2 (row pairs)
// A: [K][BB] batch-contiguous (LDG.128 -> ulonglong2 = 2 packed row-pairs, free)
// w: [K][32] warp-uniform broadcast LDS.128
__device__ __forceinline__ void gemm2(
    const float* __restrict__ A,
    const float* __restrict__ w,
    int kcnt, ull acc[2][4])
{
    #pragma unroll 8
    for (int k = 0; k < kcnt; k++) {
        ulonglong2 av = *reinterpret_cast<const ulonglong2*>(A + (size_t)k * BB);
        float4 wv = *reinterpret_cast<const float4*>(w + k * 32);
        ull w0 = pack2(wv.x, wv.x);
        ull w1 = pack2(wv.y, wv.y);
        ull w2 = pack2(wv.z, wv.z);
        ull w3 = pack2(wv.w, wv.w);
        ffma2(acc[0][0], av.x, w0);
        ffma2(acc[0][1], av.x, w1);
        ffma2(acc[0][2], av.x, w2);
        ffma2(acc[0][3], av.x, w3);
        ffma2(acc[1][0], av.y, w0);
        ffma2(acc[1][1], av.y, w1);
        ffma2(acc[1][2], av.y, w2);
        ffma2(acc[1][3], av.y, w3);
    }
}

// One LSTM layer step: CTA tile = 128 batch rows x 8 hidden units (32 z-cols).
// 512 threads, K-split across two 256-thread halves -> zsm0 / zsm1.
__device__ __forceinline__ void lstm_step(
    const float* __restrict__ Ax, int kx,          // [kx][BB] or null
    const float* __restrict__ Ah,                  // [LL][BB]
    const float* __restrict__ wsm,                 // [(kx+LL)][32]
    const float* __restrict__ bsm,
    float* __restrict__ zsm0, float* __restrict__ zsm1,
    float c2[2],
    float* __restrict__ hOutT,                     // [LL][BB]
    int b0, int nb, int tid)
{
    int half = tid >> 8;        // K-split half
    int htid = tid & 255;
    int tx = htid & 31;         // rows tx*4 .. +3
    int ty = htid >> 5;         // cols ty*4 .. +3 (warp-uniform)

    ull acc[2][4];
    #pragma unroll
    for (int i = 0; i < 2; i++)
        #pragma unroll
        for (int j = 0; j < 4; j++)
            acc[i][j] = 0ull;   // bits == {0.f, 0.f}

    int colBase = b0 + tx * 4;
    const float* wty = wsm + ty * 4;

    if (kx > 0) {
        int kh = kx >> 1;       // 64
        gemm2(Ax + colBase + (size_t)(half * kh) * BB,
              wty + (half * kh) * 32, kh, acc);
    }
    {
        int kh = LL >> 1;       // 128
        gemm2(Ah + colBase + (size_t)(half * kh) * BB,
              wty + (kx + half * kh) * 32, kh, acc);
    }

    // write partial z (padded stride -> 4-way instead of 32-way conflicts)
    float* zs = half ? zsm1 : zsm0;
    #pragma unroll
    for (int j = 0; j < 4; j++) {
        float f0, f1, f2, f3;
        unpack2(acc[0][j], f0, f1);
        unpack2(acc[1][j], f2, f3);
        int cc = ty * 4 + j;
        zs[(tx * 4 + 0) * ZST + cc] = f0;
        zs[(tx * 4 + 1) * ZST + cc] = f1;
        zs[(tx * 4 + 2) * ZST + cc] = f2;
        zs[(tx * 4 + 3) * ZST + cc] = f3;
    }
    __syncthreads();

    // activation: thread -> (2 rows, 1 unit); this mapping is FIXED (c lives here)
    int u = tid >> 6;               // 0..7
    int r0 = (tid & 63) * 2;
    float hv[2];
    #pragma unroll
    for (int i = 0; i < 2; i++) {
        int r = r0 + i;
        float zi = zsm0[r * ZST + u]      + zsm1[r * ZST + u]      + bsm[u];
        float zf = zsm0[r * ZST + 8 + u]  + zsm1[r * ZST + 8 + u]  + bsm[8 + u];
        float zg = zsm0[r * ZST + 16 + u] + zsm1[r * ZST + 16 + u] + bsm[16 + u];
        float zo = zsm0[r * ZST + 24 + u] + zsm1[r * ZST + 24 + u] + bsm[24 + u];
        float ig = sigm(zi);
        float fg = sigm(zf);
        float gg = fmaxf(zg, 0.0f);
        float og = sigm(zo);
        float cn = fg * c2[i] + ig * gg;
        c2[i] = cn;
        hv[i] = og * fmaxf(cn, 0.0f);
    }
    *reinterpret_cast<float2*>(&hOutT[(nb * 8 + u) * BB + b0 + r0]) =
        make_float2(hv[0], hv[1]);
    __syncthreads();   // protect zsm reuse
}

// Tiled transpose: encIn[b][t][k] -> g_encT[t][k][b]
extern "C" __global__ void __launch_bounds__(256)
transpose_enc_kernel(const float* __restrict__ in)
{
    __shared__ float tile[32][33];
    int t  = blockIdx.z;
    int k0 = blockIdx.y * 32;
    int b0 = blockIdx.x * 32;
    int tx = threadIdx.x, ty = threadIdx.y;  // 32 x 8
    #pragma unroll
    for (int i = 0; i < 32; i += 8)
        tile[ty + i][tx] = in[(size_t)(b0 + ty + i) * (TT * DD) + t * DD + k0 + tx];
    __syncthreads();
    #pragma unroll
    for (int i = 0; i < 32; i += 8)
        g_encT[t][k0 + ty + i][b0 + tx] = tile[tx][ty + i];
}

extern "C" __global__ void __launch_bounds__(NTHR, 1)
lstm_ae_kernel(const float* __restrict__ decIn,
               const float* __restrict__ W0, const float* __restrict__ U0, const float* __restrict__ b0g,
               const float* __restrict__ W1, const float* __restrict__ U1, const float* __restrict__ b1g,
               const float* __restrict__ Wd, const float* __restrict__ Ud, const float* __restrict__ bdg,
               const float* __restrict__ Wo, const float* __restrict__ bog,
               float* __restrict__ outp)
{
    extern __shared__ float smem[];
    float* w0sm = smem;                 // [384][32]
    float* w1sm = w0sm + 384 * 32;      // [256][32]  (W1+U1 fused: x == h for layer 1)
    float* wdsm = w1sm + 256 * 32;      // [384][32]
    float* wosm = wdsm + 384 * 32;      // [256][4]
    float* b0sm = wosm + 256 * 4;       // 32
    float* b1sm = b0sm + 32;            // 32
    float* bdsm = b1sm + 32;            // 32
    float* bosm = bdsm + 32;            // 4 (+12 pad)
    float* zsm0 = bosm + 16;            // [128][ZST]
    float* zsm1 = zsm0 + 128 * ZST;     // [128][ZST]

    int tid = threadIdx.x;
    int nb = blockIdx.x & 31;           // hidden-unit block (8 units)
    int rb = blockIdx.x >> 5;           // row block (128 batch rows)
    int b0 = rb * 128;

    // ---- one-time weight preload, layout [k][32 local cols] ----
    for (int idx = tid; idx < 384 * 32; idx += NTHR) {
        int k = idx >> 5, lc = idx & 31;
        int gcol = (lc >> 3) * LL + nb * 8 + (lc & 7);
        w0sm[idx] = (k < DD) ? W0[k * G4 + gcol] : U0[(k - DD) * G4 + gcol];
        wdsm[idx] = (k < DD) ? Wd[k * G4 + gcol] : Ud[(k - DD) * G4 + gcol];
    }
    for (int idx = tid; idx < 256 * 32; idx += NTHR) {
        int k = idx >> 5, lc = idx & 31;
        int gcol = (lc >> 3) * LL + nb * 8 + (lc & 7);
        w1sm[idx] = W1[k * G4 + gcol] + U1[k * G4 + gcol];
    }
    for (int idx = tid; idx < 256 * 4; idx += NTHR) {
        int k = idx >> 2, j = idx & 3;
        wosm[idx] = Wo[k * DD + nb * 4 + j];
    }
    if (tid < 32) {
        int gcol = (tid >> 3) * LL + nb * 8 + (tid & 7);
        b0sm[tid] = b0g[gcol];
        b1sm[tid] = b1g[gcol];
        bdsm[tid] = bdg[gcol];
    }
    if (tid < 4) bosm[tid] = bog[nb * 4 + tid];

    // zero H buffers; init decoder x(t=0) transposed
    {
        int gtid = blockIdx.x * NTHR + tid;
        float* hflat = &g_H[0][0][0];
        for (int idx = gtid; idx < 2 * LL * BB; idx += NCTA * NTHR)
            hflat[idx] = 0.0f;
        for (int idx = gtid; idx < DD * BB; idx += NCTA * NTHR) {
            int k = idx >> 9, b = idx & 511;
            g_xdT[0][k][b] = decIn[(size_t)b * (TT * DD) + k];
        }
    }

    float c2[2] = {0.0f, 0.0f};
    grid_barrier();

    int cur = 0;
    // ---------------- encoder ----------------
    for (int t = 0; t < TT; t++) {
        lstm_step(&g_encT[t][0][0], DD, &g_H[cur][0][0],
                  w0sm, b0sm, zsm0, zsm1, c2, &g_H[cur ^ 1][0][0], b0, nb, tid);
        grid_barrier();
        cur ^= 1;
        lstm_step(nullptr, 0, &g_H[cur][0][0],
                  w1sm, b1sm, zsm0, zsm1, c2, &g_H[cur ^ 1][0][0], b0, nb, tid);
        grid_barrier();
        cur ^= 1;
    }
    // ---------------- decoder ----------------
    for (int t = 0; t < TT; t++) {
        lstm_step(&g_xdT[t & 1][0][0], DD, &g_H[cur][0][0],
                  wdsm, bdsm, zsm0, zsm1, c2, &g_H[cur ^ 1][0][0], b0, nb, tid);
        grid_barrier();
        cur ^= 1;

        // out = h @ out_W + out_b : 4 out-cols x 128 rows, K split in 4 chunks
        {
            int b = tid & 127;
            int q = tid >> 7;               // 0..3 -> K chunk of 64
            const float* hP = &g_H[cur][q * 64][b0 + b];
            const float* wP = wosm + q * 64 * 4;
            float s0 = 0.f, s1 = 0.f, s2 = 0.f, s3 = 0.f;
            #pragma unroll 8
            for (int kk = 0; kk < 64; kk++) {
                float h = hP[(size_t)kk * BB];
                float4 w4 = *reinterpret_cast<const float4*>(wP + kk * 4);
                s0 = fmaf(h, w4.x, s0);
                s1 = fmaf(h, w4.y, s1);
                s2 = fmaf(h, w4.z, s2);
                s3 = fmaf(h, w4.w, s3);
            }
            if (q) {
                float* zp = zsm0 + ((q - 1) * 128 + b) * 4;
                zp[0] = s0; zp[1] = s1; zp[2] = s2; zp[3] = s3;
            }
            __syncthreads();
            if (q == 0) {
                #pragma unroll
                for (int p = 0; p < 3; p++) {
                    const float* zp = zsm0 + (p * 128 + b) * 4;
                    s0 += zp[0]; s1 += zp[1]; s2 += zp[2]; s3 += zp[3];
                }
                s0 += bosm[0]; s1 += bosm[1]; s2 += bosm[2]; s3 += bosm[3];
                *reinterpret_cast<float4*>(
                    outp + (size_t)(b0 + b) * (TT * DD) + t * DD + nb * 4) =
                    make_float4(s0, s1, s2, s3);
                int nxt = (t + 1) & 1;
                g_xdT[nxt][nb * 4 + 0][b0 + b] = s0;
                g_xdT[nxt][nb * 4 + 1][b0 + b] = s1;
                g_xdT[nxt][nb * 4 + 2][b0 + b] = s2;
                g_xdT[nxt][nb * 4 + 3][b0 + b] = s3;
            }
            __syncthreads();
        }
        grid_barrier();
    }
}

extern "C" void kernel_launch(void* const* d_in, const int* in_sizes, int n_in,
                              void* d_out, int out_size)
{
    const float* encIn = (const float*)d_in[0];
    const float* decIn = (const float*)d_in[1];
    const float* W0    = (const float*)d_in[2];
    const float* U0    = (const float*)d_in[3];
    const float* b0    = (const float*)d_in[4];
    const float* W1    = (const float*)d_in[5];
    const float* U1    = (const float*)d_in[6];
    const float* b1    = (const float*)d_in[7];
    const float* Wd    = (const float*)d_in[8];
    const float* Ud    = (const float*)d_in[9];
    const float* bd    = (const float*)d_in[10];
    const float* Wo    = (const float*)d_in[11];
    const float* bo    = (const float*)d_in[12];
    float* outp = (float*)d_out;

    // 1) transpose encoder inputs
    {
        dim3 grid(BB / 32, DD / 32, TT);
        dim3 block(32, 8);
        transpose_enc_kernel<<<grid, block>>>(encIn);
    }

    // 2) persistent LSTM kernel
    // smem floats: 12288+8192+12288+1024+112 + 2*128*33 = 42352
    size_t smem_bytes = 42352 * sizeof(float);
    cudaFuncSetAttribute((const void*)lstm_ae_kernel,
                         cudaFuncAttributeMaxDynamicSharedMemorySize, (int)smem_bytes);
    lstm_ae_kernel<<<NCTA, NTHR, smem_bytes>>>(
        decIn, W0, U0, b0, W1, U1, b1, Wd, Ud, bd, Wo, bo, outp);
}

// round 6
// speedup vs baseline: 4.7778x; 1.1535x over previous
#include <cuda_runtime.h>

#define BB 512
#define TT 512
#define DD 128
#define LL 256
#define G4 1024
#define NCTA 128
#define NTHR 512
#define NRB 4            // row blocks
#define RBCTA 32         // CTAs per row-block barrier group
#define ZST 33           // zsm row stride (bank-conflict pad)

typedef unsigned long long ull;

// Persistent state (static __device__ globals — no allocation)
__device__ float g_H[2][LL][BB];          // hidden state [feature][batch]
__device__ float g_encT[TT][DD][BB];      // encoder inputs transposed
__device__ float g_xdT[2][DD][BB];        // decoder input ping-pong, transposed
__device__ unsigned int g_count[NRB * 32];  // padded: one counter per 128B
__device__ unsigned int g_gen[NRB * 32];

// Barrier over the 32 CTAs of one row block (all h/x dependencies are row-local)
__device__ __forceinline__ void rb_barrier(int rb) {
    __syncthreads();
    if (threadIdx.x == 0) {
        volatile unsigned int* genp = &g_gen[rb * 32];
        unsigned int g = *genp;
        __threadfence();
        if (atomicAdd(&g_count[rb * 32], 1u) == RBCTA - 1u) {
            g_count[rb * 32] = 0u;
            __threadfence();
            *genp = g + 1u;
        } else {
            while (*genp == g) { }
        }
        __threadfence();
    }
    __syncthreads();
}

__device__ __forceinline__ float sigm(float x) { return 1.0f / (1.0f + __expf(-x)); }

__device__ __forceinline__ ull pack2(float lo, float hi) {
    ull r; asm("mov.b64 %0, {%1, %2};" : "=l"(r) : "f"(lo), "f"(hi)); return r;
}
__device__ __forceinline__ void unpack2(ull v, float& lo, float& hi) {
    asm("mov.b64 {%0, %1}, %2;" : "=f"(lo), "=f"(hi) : "l"(v));
}
__device__ __forceinline__ void ffma2(ull& d, ull a, ull b) {
    asm("fma.rn.f32x2 %0, %1, %2, %0;" : "+l"(d) : "l"(a), "l"(b));
}

// acc[rp][j] (+)= A[k][4 rows] * W[k][8 cols]; 16 FFMA2 per k.
// A: [K][BB] batch-contiguous (one LDG.128 per thread per k)
// w: [K][32], thread reads 8 warp-uniform cols (2 broadcast LDS.128)
__device__ __forceinline__ void gemm48(
    const float* __restrict__ A,
    const float* __restrict__ w,      // pre-offset to this thread's 8 cols
    int kcnt, ull acc[2][8])
{
    #pragma unroll 4
    for (int k = 0; k < kcnt; k++) {
        ulonglong2 av = *reinterpret_cast<const ulonglong2*>(A + (size_t)k * BB);
        float4 wa = *reinterpret_cast<const float4*>(w + k * 32);
        float4 wb = *reinterpret_cast<const float4*>(w + k * 32 + 4);
        ull w0 = pack2(wa.x, wa.x);
        ull w1 = pack2(wa.y, wa.y);
        ull w2 = pack2(wa.z, wa.z);
        ull w3 = pack2(wa.w, wa.w);
        ull w4 = pack2(wb.x, wb.x);
        ull w5 = pack2(wb.y, wb.y);
        ull w6 = pack2(wb.z, wb.z);
        ull w7 = pack2(wb.w, wb.w);
        ffma2(acc[0][0], av.x, w0);
        ffma2(acc[0][1], av.x, w1);
        ffma2(acc[0][2], av.x, w2);
        ffma2(acc[0][3], av.x, w3);
        ffma2(acc[0][4], av.x, w4);
        ffma2(acc[0][5], av.x, w5);
        ffma2(acc[0][6], av.x, w6);
        ffma2(acc[0][7], av.x, w7);
        ffma2(acc[1][0], av.y, w0);
        ffma2(acc[1][1], av.y, w1);
        ffma2(acc[1][2], av.y, w2);
        ffma2(acc[1][3], av.y, w3);
        ffma2(acc[1][4], av.y, w4);
        ffma2(acc[1][5], av.y, w5);
        ffma2(acc[1][6], av.y, w6);
        ffma2(acc[1][7], av.y, w7);
    }
}

// One LSTM layer step: CTA tile = 128 batch rows x 8 hidden units (32 z-cols).
// 512 threads = 4 K-quarters x 128; quarter q writes partial z to zsm[q].
__device__ __forceinline__ void lstm_step(
    const float* __restrict__ Ax, int kx,          // [kx][BB] or null
    const float* __restrict__ Ah,                  // [LL][BB]
    const float* __restrict__ wsm,                 // [(kx+LL)][32]
    const float* __restrict__ bsm,
    float* __restrict__ zsm,                       // [4][128][ZST]
    float c2[2],
    float* __restrict__ hOutT,                     // [LL][BB]
    int b0, int nb, int tid)
{
    int q    = tid >> 7;        // K quarter
    int qtid = tid & 127;
    int tx   = qtid & 31;       // rows tx*4 .. +3
    int ty   = qtid >> 5;       // cols ty*8 .. +7 (warp-uniform)

    ull acc[2][8];
    #pragma unroll
    for (int i = 0; i < 2; i++)
        #pragma unroll
        for (int j = 0; j < 8; j++)
            acc[i][j] = 0ull;

    int colBase = b0 + tx * 4;
    const float* wty = wsm + ty * 8;

    if (kx > 0) {
        int kq = kx >> 2;       // 32
        gemm48(Ax + colBase + (size_t)(q * kq) * BB, wty + (q * kq) * 32, kq, acc);
    }
    {
        int kq = LL >> 2;       // 64
        gemm48(Ah + colBase + (size_t)(q * kq) * BB, wty + (kx + q * kq) * 32, kq, acc);
    }

    // write partial z (SCALAR stores: ZST=33 keeps conflicts at 4-way;
    // float2 here would be 8-byte-misaligned on odd rows)
    float* zs = zsm + q * (128 * ZST);
    #pragma unroll
    for (int j = 0; j < 8; j++) {
        float f0, f1, f2, f3;
        unpack2(acc[0][j], f0, f1);
        unpack2(acc[1][j], f2, f3);
        int cc = ty * 8 + j;
        zs[(tx * 4 + 0) * ZST + cc] = f0;
        zs[(tx * 4 + 1) * ZST + cc] = f1;
        zs[(tx * 4 + 2) * ZST + cc] = f2;
        zs[(tx * 4 + 3) * ZST + cc] = f3;
    }
    __syncthreads();

    // activation: thread -> (2 rows, 1 unit); FIXED mapping (c lives here)
    int u  = tid >> 6;              // 0..7
    int r0 = (tid & 63) * 2;
    float hv[2];
    #pragma unroll
    for (int i = 0; i < 2; i++) {
        int r = r0 + i;
        float zi = bsm[u],      zf = bsm[8 + u];
        float zg = bsm[16 + u], zo = bsm[24 + u];
        #pragma unroll
        for (int p = 0; p < 4; p++) {
            const float* zp = zsm + p * (128 * ZST) + r * ZST;
            zi += zp[u];
            zf += zp[8 + u];
            zg += zp[16 + u];
            zo += zp[24 + u];
        }
        float ig = sigm(zi);
        float fg = sigm(zf);
        float gg = fmaxf(zg, 0.0f);
        float og = sigm(zo);
        float cn = fg * c2[i] + ig * gg;
        c2[i] = cn;
        hv[i] = og * fmaxf(cn, 0.0f);
    }
    *reinterpret_cast<float2*>(&hOutT[(nb * 8 + u) * BB + b0 + r0]) =
        make_float2(hv[0], hv[1]);
    __syncthreads();   // protect zsm reuse
}

// Tiled transpose: encIn[b][t][k] -> g_encT[t][k][b]
extern "C" __global__ void __launch_bounds__(256)
transpose_enc_kernel(const float* __restrict__ in)
{
    __shared__ float tile[32][33];
    int t  = blockIdx.z;
    int k0 = blockIdx.y * 32;
    int b0 = blockIdx.x * 32;
    int tx = threadIdx.x, ty = threadIdx.y;  // 32 x 8
    #pragma unroll
    for (int i = 0; i < 32; i += 8)
        tile[ty + i][tx] = in[(size_t)(b0 + ty + i) * (TT * DD) + t * DD + k0 + tx];
    __syncthreads();
    #pragma unroll
    for (int i = 0; i < 32; i += 8)
        g_encT[t][k0 + ty + i][b0 + tx] = tile[tx][ty + i];
}

extern "C" __global__ void __launch_bounds__(NTHR, 1)
lstm_ae_kernel(const float* __restrict__ decIn,
               const float* __restrict__ W0, const float* __restrict__ U0, const float* __restrict__ b0g,
               const float* __restrict__ W1, const float* __restrict__ U1, const float* __restrict__ b1g,
               const float* __restrict__ Wd, const float* __restrict__ Ud, const float* __restrict__ bdg,
               const float* __restrict__ Wo, const float* __restrict__ bog,
               float* __restrict__ outp)
{
    extern __shared__ float smem[];
    float* w0sm = smem;                 // [384][32]
    float* w1sm = w0sm + 384 * 32;      // [256][32]  (W1+U1 fused: x == h for layer 1)
    float* wdsm = w1sm + 256 * 32;      // [384][32]
    float* wosm = wdsm + 384 * 32;      // [256][4]
    float* b0sm = wosm + 256 * 4;       // 32
    float* b1sm = b0sm + 32;            // 32
    float* bdsm = b1sm + 32;            // 32
    float* bosm = bdsm + 32;            // 4 (+12 pad)
    float* zsm  = bosm + 16;            // [4][128][ZST]

    int tid = threadIdx.x;
    int nb = blockIdx.x & 31;           // hidden-unit block (8 units)
    int rb = blockIdx.x >> 5;           // row block (128 batch rows)
    int b0 = rb * 128;

    // ---- one-time weight preload, layout [k][32 local cols] ----
    for (int idx = tid; idx < 384 * 32; idx += NTHR) {
        int k = idx >> 5, lc = idx & 31;
        int gcol = (lc >> 3) * LL + nb * 8 + (lc & 7);
        w0sm[idx] = (k < DD) ? W0[k * G4 + gcol] : U0[(k - DD) * G4 + gcol];
        wdsm[idx] = (k < DD) ? Wd[k * G4 + gcol] : Ud[(k - DD) * G4 + gcol];
    }
    for (int idx = tid; idx < 256 * 32; idx += NTHR) {
        int k = idx >> 5, lc = idx & 31;
        int gcol = (lc >> 3) * LL + nb * 8 + (lc & 7);
        w1sm[idx] = W1[k * G4 + gcol] + U1[k * G4 + gcol];
    }
    for (int idx = tid; idx < 256 * 4; idx += NTHR) {
        int k = idx >> 2, j = idx & 3;
        wosm[idx] = Wo[k * DD + nb * 4 + j];
    }
    if (tid < 32) {
        int gcol = (tid >> 3) * LL + nb * 8 + (tid & 7);
        b0sm[tid] = b0g[gcol];
        b1sm[tid] = b1g[gcol];
        bdsm[tid] = bdg[gcol];
    }
    if (tid < 4) bosm[tid] = bog[nb * 4 + tid];

    // init: each CTA owns its (feature-slice x batch-slice) of g_H / g_xdT,
    // matching exactly what same-rb CTAs will read -> rb barrier suffices.
    for (int idx = tid; idx < 2 * 8 * 128; idx += NTHR) {
        int buf = idx >> 10, f = (idx >> 7) & 7, b = idx & 127;
        g_H[buf][nb * 8 + f][b0 + b] = 0.0f;
    }
    for (int idx = tid; idx < 4 * 128; idx += NTHR) {
        int f = idx >> 7, b = idx & 127;
        g_xdT[0][nb * 4 + f][b0 + b] = decIn[(size_t)(b0 + b) * (TT * DD) + nb * 4 + f];
    }

    float c2[2] = {0.0f, 0.0f};
    rb_barrier(rb);

    int cur = 0;
    // ---------------- encoder ----------------
    for (int t = 0; t < TT; t++) {
        lstm_step(&g_encT[t][0][0], DD, &g_H[cur][0][0],
                  w0sm, b0sm, zsm, c2, &g_H[cur ^ 1][0][0], b0, nb, tid);
        rb_barrier(rb);
        cur ^= 1;
        lstm_step(nullptr, 0, &g_H[cur][0][0],
                  w1sm, b1sm, zsm, c2, &g_H[cur ^ 1][0][0], b0, nb, tid);
        rb_barrier(rb);
        cur ^= 1;
    }
    // ---------------- decoder ----------------
    for (int t = 0; t < TT; t++) {
        lstm_step(&g_xdT[t & 1][0][0], DD, &g_H[cur][0][0],
                  wdsm, bdsm, zsm, c2, &g_H[cur ^ 1][0][0], b0, nb, tid);
        rb_barrier(rb);
        cur ^= 1;

        // out = h @ out_W + out_b : 4 out-cols x 128 rows, K split in 4 chunks
        {
            int b = tid & 127;
            int q = tid >> 7;               // 0..3 -> K chunk of 64
            const float* hP = &g_H[cur][q * 64][b0 + b];
            const float* wP = wosm + q * 64 * 4;
            float s0 = 0.f, s1 = 0.f, s2 = 0.f, s3 = 0.f;
            #pragma unroll 8
            for (int kk = 0; kk < 64; kk++) {
                float h = hP[(size_t)kk * BB];
                float4 w4 = *reinterpret_cast<const float4*>(wP + kk * 4);
                s0 = fmaf(h, w4.x, s0);
                s1 = fmaf(h, w4.y, s1);
                s2 = fmaf(h, w4.z, s2);
                s3 = fmaf(h, w4.w, s3);
            }
            if (q) {
                float* zp = zsm + ((q - 1) * 128 + b) * 4;
                zp[0] = s0; zp[1] = s1; zp[2] = s2; zp[3] = s3;
            }
            __syncthreads();
            if (q == 0) {
                #pragma unroll
                for (int p = 0; p < 3; p++) {
                    const float* zp = zsm + (p * 128 + b) * 4;
                    s0 += zp[0]; s1 += zp[1]; s2 += zp[2]; s3 += zp[3];
                }
                s0 += bosm[0]; s1 += bosm[1]; s2 += bosm[2]; s3 += bosm[3];
                *reinterpret_cast<float4*>(
                    outp + (size_t)(b0 + b) * (TT * DD) + t * DD + nb * 4) =
                    make_float4(s0, s1, s2, s3);
                int nxt = (t + 1) & 1;
                g_xdT[nxt][nb * 4 + 0][b0 + b] = s0;
                g_xdT[nxt][nb * 4 + 1][b0 + b] = s1;
                g_xdT[nxt][nb * 4 + 2][b0 + b] = s2;
                g_xdT[nxt][nb * 4 + 3][b0 + b] = s3;
            }
            __syncthreads();
        }
        rb_barrier(rb);
    }
}

extern "C" void kernel_launch(void* const* d_in, const int* in_sizes, int n_in,
                              void* d_out, int out_size)
{
    const float* encIn = (const float*)d_in[0];
    const float* decIn = (const float*)d_in[1];
    const float* W0    = (const float*)d_in[2];
    const float* U0    = (const float*)d_in[3];
    const float* b0    = (const float*)d_in[4];
    const float* W1    = (const float*)d_in[5];
    const float* U1    = (const float*)d_in[6];
    const float* b1    = (const float*)d_in[7];
    const float* Wd    = (const float*)d_in[8];
    const float* Ud    = (const float*)d_in[9];
    const float* bd    = (const float*)d_in[10];
    const float* Wo    = (const float*)d_in[11];
    const float* bo    = (const float*)d_in[12];
    float* outp = (float*)d_out;

    // 1) transpose encoder inputs
    {
        dim3 grid(BB / 32, DD / 32, TT);
        dim3 block(32, 8);
        transpose_enc_kernel<<<grid, block>>>(encIn);
    }

    // 2) persistent LSTM kernel
    // smem floats: 12288+8192+12288+1024+112 + 4*128*33 = 50800 (203.2KB)
    size_t smem_bytes = 50800 * sizeof(float);
    cudaFuncSetAttribute((const void*)lstm_ae_kernel,
                         cudaFuncAttributeMaxDynamicSharedMemorySize, (int)smem_bytes);
    lstm_ae_kernel<<<NCTA, NTHR, smem_bytes>>>(
        decIn, W0, U0, b0, W1, U1, b1, Wd, Ud, bd, Wo, bo, outp);
}